// round 14
// baseline (speedup 1.0000x reference)
#include <cuda_runtime.h>
#include <cuda_fp16.h>
#include <stdint.h>

// Problem constants (fixed-shape problem)
#define NROWS 65536              // 256*256 neurons
#define BATCH 64
#define SYN   33                 // 32 random + 1 self synapse per source neuron
#define CAP   1024               // ELL row capacity (corner rows reach ~700 due to clamping)

#define NNZ_FIX   (NROWS * SYN)          // 2,162,688
#define NQ_FIX    (NNZ_FIX / 4)          // 540,672 quads
#define SCATTER_BLOCKS ((NQ_FIX + 255) / 256)   // 2112  (was WRONGLY 528 in R13)
#define TRANSPOSE_BLOCKS (NROWS / 32)           // 2048

// ---------------- device scratch (static; no runtime allocation) ----------------
// g_counts is zero at module load; spmm re-zeros each row after reading it, so
// every call's scatter starts from a clean histogram (self-cleaning pipeline).
__device__ __half g_xt[NROWS * BATCH];           // x transposed, fp16: [N, 64] (128 B/row)
__device__ int    g_counts[NROWS];               // per-destination-row edge count
__device__ float2 g_ell[(size_t)NROWS * CAP];    // (value, col-as-bits) per slot

// ---------------- 1. fused build: scatter (blocks 0..2111) + transpose (rest) ----------------
__global__ void build_kernel(const float* __restrict__ x,
                             const int4* __restrict__ rows4,
                             const float4* __restrict__ vals4, int nq) {
    int t = threadIdx.x;     // 0..255

    if (blockIdx.x < SCATTER_BLOCKS) {
        // ---- scatter edges into ELL (hist fused; 4 edges/thread) ----
        // cols structurally determined: col[e] = e / 33 (source-major repeat).
        int q = blockIdx.x * 256 + t;
        if (q < nq) {
            int4   r = rows4[q];
            float4 v = vals4[q];
            int e0 = q << 2;
            int c0 = (int)((unsigned)e0 / SYN);
            int c1 = (int)((unsigned)(e0 + 1) / SYN);
            int c2 = (int)((unsigned)(e0 + 2) / SYN);
            int c3 = (int)((unsigned)(e0 + 3) / SYN);
            // 4 independent atomic->store chains
            int p0 = atomicAdd(&g_counts[r.x], 1);
            int p1 = atomicAdd(&g_counts[r.y], 1);
            int p2 = atomicAdd(&g_counts[r.z], 1);
            int p3 = atomicAdd(&g_counts[r.w], 1);
            if (p0 < CAP) g_ell[((size_t)r.x << 10) + p0] = make_float2(v.x, __int_as_float(c0));
            if (p1 < CAP) g_ell[((size_t)r.y << 10) + p1] = make_float2(v.y, __int_as_float(c1));
            if (p2 < CAP) g_ell[((size_t)r.z << 10) + p2] = make_float2(v.z, __int_as_float(c2));
            if (p3 < CAP) g_ell[((size_t)r.w << 10) + p3] = make_float2(v.w, __int_as_float(c3));
        }
    } else {
        // ---- transpose x [64, N] -> xt [N, 64] fp16 (full 128B line writes) ----
        __shared__ float s[64][33];
        int n0 = (blockIdx.x - SCATTER_BLOCKS) * 32;
        int tx = t & 31;     // 0..31
        int ty = t >> 5;     // 0..7
#pragma unroll
        for (int k = 0; k < 8; k++) {
            int b = ty + k * 8;
            s[b][tx] = x[(size_t)b * NROWS + n0 + tx];
        }
        __syncthreads();
        unsigned int* dst = (unsigned int*)g_xt;     // [N][32] half2-as-uint
#pragma unroll
        for (int k = 0; k < 4; k++) {
            int n = ty + k * 8;                      // local neuron 0..31
            __half2 h = __floats2half2_rn(s[2 * tx][n], s[2 * tx + 1][n]);
            dst[(size_t)(n0 + n) * 32 + tx] = *(unsigned int*)&h;   // one 128B line/row
        }
    }
}

// tail (nnz not divisible by 4) — never launched for this shape, kept for safety
__global__ void scatter_tail_kernel(const int* __restrict__ rows,
                                    const float* __restrict__ vals,
                                    int start, int nnz) {
    int e = start + blockIdx.x * blockDim.x + threadIdx.x;
    if (e < nnz) {
        int r = rows[e];
        int c = (int)((unsigned)e / SYN);
        int pos = atomicAdd(&g_counts[r], 1);
        if (pos < CAP)
            g_ell[((size_t)r << 10) + pos] = make_float2(vals[e], __int_as_float(c));
    }
}

// ---------------- 2. gather SpMM: out[b, r] = sum_e v_e * xt[col_e][b] ----------------
// Proven-best R9 structure: warp = 1 row; 4 lane-groups = 4 edge subsets;
// lane-in-group oct covers batch halves oct*8..oct*8+7 (fp16 row = 128 B =
// 8 uint4 lanes). 16 edges/iteration: 4 uniform LDG.64 edge loads + 4
// independent LDG.128 gathers in flight. Groups combined with shfl_xor(8,16).
// Lane 0 resets g_counts[r] = 0 after reading (self-clean for next call).
__global__ void __launch_bounds__(512, 2) spmm_kernel(float* __restrict__ out) {
    __shared__ float tile[16 * 65];   // [row_local][b]
    const int t = threadIdx.x;
    const int warp = t >> 5;
    const int lane = t & 31;
    const int grp = lane >> 3;        // 0..3: edge subset within iteration
    const int oct = lane & 7;         // batch halves oct*8 .. oct*8+7
    const int r0 = blockIdx.x * 16;
    const int r = r0 + warp;

    int cnt = g_counts[r];
    if (lane == 0) g_counts[r] = 0;   // self-clean for next call
    if (cnt > CAP) cnt = CAP;
    const float2* __restrict__ ell = &g_ell[(size_t)r << 10];
    const uint4* __restrict__ xt8 = (const uint4*)g_xt;   // [N][8] uint4

    float acc[8] = {0.f, 0.f, 0.f, 0.f, 0.f, 0.f, 0.f, 0.f};

    for (int j = 0; j < cnt; j += 16) {      // 16 edges per iteration
        float v[4];
        int   c[4];
        uint4 xv[4];
#pragma unroll
        for (int u = 0; u < 4; u++) {        // 4 edge loads, uniform per 8-lane group
            int idx = j + (u << 2) + grp;
            float2 e = (idx < cnt) ? __ldg(&ell[idx])
                                   : make_float2(0.f, __int_as_float(0));
            v[u] = e.x;
            c[u] = __float_as_int(e.y);
        }
#pragma unroll
        for (int u = 0; u < 4; u++)          // 4 LDG.128 = 16 edges in flight
            xv[u] = __ldg(&xt8[(c[u] << 3) + oct]);
#pragma unroll
        for (int u = 0; u < 4; u++) {
            const __half2* h = (const __half2*)&xv[u];
#pragma unroll
            for (int k = 0; k < 4; k++) {
                float2 f = __half22float2(h[k]);
                acc[2 * k]     = fmaf(v[u], f.x, acc[2 * k]);
                acc[2 * k + 1] = fmaf(v[u], f.y, acc[2 * k + 1]);
            }
        }
    }

    // combine the 4 edge-subset groups (lanes l, l+8, l+16, l+24 share oct)
#pragma unroll
    for (int k = 0; k < 8; k++) {
        acc[k] += __shfl_xor_sync(0xffffffffu, acc[k], 8);
        acc[k] += __shfl_xor_sync(0xffffffffu, acc[k], 16);
    }

    if (grp == 0) {
        int base = warp * 65 + oct * 8;
#pragma unroll
        for (int k = 0; k < 8; k++) tile[base + k] = acc[k];
    }
    __syncthreads();
#pragma unroll
    for (int k = 0; k < 2; k++) {
        int idx = k * 512 + t;
        int b = idx >> 4;        // 0..63
        int c = idx & 15;        // 0..15
        out[b * NROWS + r0 + c] = tile[c * 65 + b];
    }
}

// ---------------- launch ----------------
extern "C" void kernel_launch(void* const* d_in, const int* in_sizes, int n_in,
                              void* d_out, int out_size) {
    const float* x    = (const float*)d_in[0];   // [64, 65536]
    const float* vals = (const float*)d_in[1];   // [NNZ]
    const int*   rows = (const int*)d_in[2];     // [NNZ] int32
    float* out = (float*)d_out;                  // [64, 65536]
    int nnz = in_sizes[1];

    // fused build: scatter (histogram fused; counts pre-zeroed by prior spmm
    // or by static zero-init) overlapped with fp16 transpose
    int nq = nnz >> 2;
    build_kernel<<<SCATTER_BLOCKS + TRANSPOSE_BLOCKS, 256>>>(
        x, (const int4*)rows, (const float4*)vals, nq);
    int done = nq << 2;
    if (done < nnz) {
        int rem = nnz - done;
        scatter_tail_kernel<<<(rem + 255) / 256, 256>>>(rows, vals, done, nnz);
    }
    // gather SpMM (also re-zeros g_counts for the next call)
    spmm_kernel<<<NROWS / 16, 512>>>(out);
}

// round 15
// speedup vs baseline: 2.1802x; 2.1802x over previous
#include <cuda_runtime.h>
#include <cuda_fp16.h>
#include <stdint.h>

// Problem constants (fixed-shape problem)
#define NROWS 65536              // 256*256 neurons
#define BATCH 64
#define SYN   33                 // 32 random + 1 self synapse per source neuron
#define CAP   1024               // ELL row capacity (corner rows reach ~700 due to clamping)

// ---------------- device scratch (static; no runtime allocation) ----------------
__device__ __half g_xt[NROWS * BATCH];           // x transposed, fp16: [N, 64] (128 B/row)
__device__ int    g_counts[NROWS];               // per-destination-row edge count
__device__ float2 g_ell[(size_t)NROWS * CAP];    // (value, col-as-bits) per slot

// ---------------- 1. transpose x [64, N] -> xt [N, 64] fp16  (+ fused counts zeroing) ----------------
// Block = 32 neurons x ALL 64 batch: each output row (128 B) written as one
// full line (32 lanes x half2). Grid = 2048 blocks.
__global__ void transpose_kernel(const float* __restrict__ x) {
    __shared__ float s[64][33];
    int n0 = blockIdx.x * 32;
    int tx = threadIdx.x;       // 0..31
    int ty = threadIdx.y;       // 0..7

    // fused: zero g_counts (blocks 0..255 cover 65536 ints)
    if (blockIdx.x < 256) {
        g_counts[blockIdx.x * 256 + ty * 32 + tx] = 0;
    }

#pragma unroll
    for (int k = 0; k < 8; k++) {
        int b = ty + k * 8;
        s[b][tx] = x[(size_t)b * NROWS + n0 + tx];
    }
    __syncthreads();
    unsigned int* dst = (unsigned int*)g_xt;     // [N][32] half2-as-uint
#pragma unroll
    for (int k = 0; k < 4; k++) {
        int n = ty + k * 8;                      // local neuron 0..31
        __half2 h = __floats2half2_rn(s[2 * tx][n], s[2 * tx + 1][n]);
        dst[(size_t)(n0 + n) * 32 + tx] = *(unsigned int*)&h;   // one 128B line/row
    }
}

// ---------------- 2. scatter edges into ELL (hist fused; 4 edges/thread) ----------------
// cols is structurally determined: col[e] = e / 33 (source-major repeat) — not read.
__global__ void scatter_kernel(const int4* __restrict__ rows4,
                               const float4* __restrict__ vals4, int nq) {
    int q = blockIdx.x * blockDim.x + threadIdx.x;
    if (q < nq) {
        int4   r = rows4[q];
        float4 v = vals4[q];
        int e0 = q << 2;
        int c0 = (int)((unsigned)e0 / SYN);
        int c1 = (int)((unsigned)(e0 + 1) / SYN);
        int c2 = (int)((unsigned)(e0 + 2) / SYN);
        int c3 = (int)((unsigned)(e0 + 3) / SYN);
        // 4 independent atomic->store chains
        int p0 = atomicAdd(&g_counts[r.x], 1);
        int p1 = atomicAdd(&g_counts[r.y], 1);
        int p2 = atomicAdd(&g_counts[r.z], 1);
        int p3 = atomicAdd(&g_counts[r.w], 1);
        if (p0 < CAP) g_ell[((size_t)r.x << 10) + p0] = make_float2(v.x, __int_as_float(c0));
        if (p1 < CAP) g_ell[((size_t)r.y << 10) + p1] = make_float2(v.y, __int_as_float(c1));
        if (p2 < CAP) g_ell[((size_t)r.z << 10) + p2] = make_float2(v.z, __int_as_float(c2));
        if (p3 < CAP) g_ell[((size_t)r.w << 10) + p3] = make_float2(v.w, __int_as_float(c3));
    }
}
// tail (nnz not divisible by 4) — never launched for this shape, kept for safety
__global__ void scatter_tail_kernel(const int* __restrict__ rows,
                                    const float* __restrict__ vals,
                                    int start, int nnz) {
    int e = start + blockIdx.x * blockDim.x + threadIdx.x;
    if (e < nnz) {
        int r = rows[e];
        int c = (int)((unsigned)e / SYN);
        int pos = atomicAdd(&g_counts[r], 1);
        if (pos < CAP)
            g_ell[((size_t)r << 10) + pos] = make_float2(vals[e], __int_as_float(c));
    }
}

// ---------------- 3. gather SpMM: out[b, r] = sum_e v_e * xt[col_e][b] ----------------
// Proven-best R9 structure, byte-identical inner loop: warp = 1 row; 4 lane-
// groups = 4 edge subsets; lane-in-group oct covers batch halves oct*8..oct*8+7
// (fp16 row = 128 B = 8 uint4 lanes). 16 edges/iteration: 4 uniform LDG.64 edge
// loads + 4 independent LDG.128 gathers in flight. Groups combined with
// shfl_xor(8,16). NEW (zero-risk): boustrophedon block remap so the heavy
// corner-row blocks (cnt~650, ~41 iterations) start in wave 1 instead of the
// last wave, removing the straggler tail.
__global__ void __launch_bounds__(512, 2) spmm_kernel(float* __restrict__ out) {
    __shared__ float tile[16 * 65];   // [row_local][b]
    const int t = threadIdx.x;
    const int warp = t >> 5;
    const int lane = t & 31;
    const int grp = lane >> 3;        // 0..3: edge subset within iteration
    const int oct = lane & 7;         // batch halves oct*8 .. oct*8+7
    // boustrophedon remap: even bids walk up from 0, odd bids walk down from nb-1
    const int nb = gridDim.x;
    const int bid = blockIdx.x;
    const int mapped = (bid & 1) ? (nb - 1 - (bid >> 1)) : (bid >> 1);
    const int r0 = mapped * 16;
    const int r = r0 + warp;

    int cnt = g_counts[r];
    if (cnt > CAP) cnt = CAP;
    const float2* __restrict__ ell = &g_ell[(size_t)r << 10];
    const uint4* __restrict__ xt8 = (const uint4*)g_xt;   // [N][8] uint4

    float acc[8] = {0.f, 0.f, 0.f, 0.f, 0.f, 0.f, 0.f, 0.f};

    for (int j = 0; j < cnt; j += 16) {      // 16 edges per iteration
        float v[4];
        int   c[4];
        uint4 xv[4];
#pragma unroll
        for (int u = 0; u < 4; u++) {        // 4 edge loads, uniform per 8-lane group
            int idx = j + (u << 2) + grp;
            float2 e = (idx < cnt) ? __ldg(&ell[idx])
                                   : make_float2(0.f, __int_as_float(0));
            v[u] = e.x;
            c[u] = __float_as_int(e.y);
        }
#pragma unroll
        for (int u = 0; u < 4; u++)          // 4 LDG.128 = 16 edges in flight
            xv[u] = __ldg(&xt8[(c[u] << 3) + oct]);
#pragma unroll
        for (int u = 0; u < 4; u++) {
            const __half2* h = (const __half2*)&xv[u];
#pragma unroll
            for (int k = 0; k < 4; k++) {
                float2 f = __half22float2(h[k]);
                acc[2 * k]     = fmaf(v[u], f.x, acc[2 * k]);
                acc[2 * k + 1] = fmaf(v[u], f.y, acc[2 * k + 1]);
            }
        }
    }

    // combine the 4 edge-subset groups (lanes l, l+8, l+16, l+24 share oct)
#pragma unroll
    for (int k = 0; k < 8; k++) {
        acc[k] += __shfl_xor_sync(0xffffffffu, acc[k], 8);
        acc[k] += __shfl_xor_sync(0xffffffffu, acc[k], 16);
    }

    if (grp == 0) {
        int base = warp * 65 + oct * 8;
#pragma unroll
        for (int k = 0; k < 8; k++) tile[base + k] = acc[k];
    }
    __syncthreads();
#pragma unroll
    for (int k = 0; k < 2; k++) {
        int idx = k * 512 + t;
        int b = idx >> 4;        // 0..63
        int c = idx & 15;        // 0..15
        out[b * NROWS + r0 + c] = tile[c * 65 + b];
    }
}

// ---------------- launch ----------------
extern "C" void kernel_launch(void* const* d_in, const int* in_sizes, int n_in,
                              void* d_out, int out_size) {
    const float* x    = (const float*)d_in[0];   // [64, 65536]
    const float* vals = (const float*)d_in[1];   // [NNZ]
    const int*   rows = (const int*)d_in[2];     // [NNZ] int32
    float* out = (float*)d_out;                  // [64, 65536]
    int nnz = in_sizes[1];

    // transpose x -> xt [N, 64] fp16  (also zeroes g_counts)
    {
        dim3 blk(32, 8);
        dim3 grd(NROWS / 32, 1);
        transpose_kernel<<<grd, blk>>>(x);
    }
    // ELL build: scatter with fused histogram (4 edges/thread; cols computed)
    int nq = nnz >> 2;
    if (nq > 0)
        scatter_kernel<<<(nq + 255) / 256, 256>>>(
            (const int4*)rows, (const float4*)vals, nq);
    int done = nq << 2;
    if (done < nnz) {
        int rem = nnz - done;
        scatter_tail_kernel<<<(rem + 255) / 256, 256>>>(rows, vals, done, nnz);
    }
    // gather SpMM
    spmm_kernel<<<NROWS / 16, 512>>>(out);
}

// round 16
// speedup vs baseline: 2.2288x; 1.0223x over previous
#include <cuda_runtime.h>
#include <cuda_fp16.h>
#include <stdint.h>

// Problem constants (fixed-shape problem)
#define NROWS 65536              // 256*256 neurons
#define BATCH 64
#define SYN   33                 // 32 random + 1 self synapse per source neuron
#define CAP   1024               // ELL row capacity (corner rows reach ~700 due to clamping)

// ---------------- device scratch (static; no runtime allocation) ----------------
__device__ __half   g_xt[NROWS * BATCH];         // x transposed, fp16: [N, 64] (128 B/row)
__device__ int      g_counts[NROWS];             // per-destination-row edge count
__device__ uint32_t g_ell[(size_t)NROWS * CAP];  // packed edge: (col << 16) | half(value)

// ---------------- 1. transpose x [64, N] -> xt [N, 64] fp16  (+ fused counts zeroing) ----------------
// Block = 32 neurons x ALL 64 batch: each output row (128 B) written as one
// full line (32 lanes x half2). Grid = 2048 blocks.
__global__ void transpose_kernel(const float* __restrict__ x) {
    __shared__ float s[64][33];
    int n0 = blockIdx.x * 32;
    int tx = threadIdx.x;       // 0..31
    int ty = threadIdx.y;       // 0..7

    // fused: zero g_counts (blocks 0..255 cover 65536 ints)
    if (blockIdx.x < 256) {
        g_counts[blockIdx.x * 256 + ty * 32 + tx] = 0;
    }

#pragma unroll
    for (int k = 0; k < 8; k++) {
        int b = ty + k * 8;
        s[b][tx] = x[(size_t)b * NROWS + n0 + tx];
    }
    __syncthreads();
    unsigned int* dst = (unsigned int*)g_xt;     // [N][32] half2-as-uint
#pragma unroll
    for (int k = 0; k < 4; k++) {
        int n = ty + k * 8;                      // local neuron 0..31
        __half2 h = __floats2half2_rn(s[2 * tx][n], s[2 * tx + 1][n]);
        dst[(size_t)(n0 + n) * 32 + tx] = *(unsigned int*)&h;   // one 128B line/row
    }
}

// ---------------- 2. scatter edges into packed ELL (hist fused; 4 edges/thread) ----------------
// cols structurally determined: col[e] = e / 33 (source-major repeat) — not read.
// Entry = (col << 16) | fp16(value): 4 bytes instead of 8.
__device__ __forceinline__ uint32_t pack_edge(float v, int c) {
    return ((uint32_t)c << 16) | (uint32_t)__half_as_ushort(__float2half(v));
}
__global__ void scatter_kernel(const int4* __restrict__ rows4,
                               const float4* __restrict__ vals4, int nq) {
    int q = blockIdx.x * blockDim.x + threadIdx.x;
    if (q < nq) {
        int4   r = rows4[q];
        float4 v = vals4[q];
        int e0 = q << 2;
        int c0 = (int)((unsigned)e0 / SYN);
        int c1 = (int)((unsigned)(e0 + 1) / SYN);
        int c2 = (int)((unsigned)(e0 + 2) / SYN);
        int c3 = (int)((unsigned)(e0 + 3) / SYN);
        // 4 independent atomic->store chains
        int p0 = atomicAdd(&g_counts[r.x], 1);
        int p1 = atomicAdd(&g_counts[r.y], 1);
        int p2 = atomicAdd(&g_counts[r.z], 1);
        int p3 = atomicAdd(&g_counts[r.w], 1);
        if (p0 < CAP) g_ell[((size_t)r.x << 10) + p0] = pack_edge(v.x, c0);
        if (p1 < CAP) g_ell[((size_t)r.y << 10) + p1] = pack_edge(v.y, c1);
        if (p2 < CAP) g_ell[((size_t)r.z << 10) + p2] = pack_edge(v.z, c2);
        if (p3 < CAP) g_ell[((size_t)r.w << 10) + p3] = pack_edge(v.w, c3);
    }
}
// tail (nnz not divisible by 4) — never launched for this shape, kept for safety
__global__ void scatter_tail_kernel(const int* __restrict__ rows,
                                    const float* __restrict__ vals,
                                    int start, int nnz) {
    int e = start + blockIdx.x * blockDim.x + threadIdx.x;
    if (e < nnz) {
        int r = rows[e];
        int c = (int)((unsigned)e / SYN);
        int pos = atomicAdd(&g_counts[r], 1);
        if (pos < CAP)
            g_ell[((size_t)r << 10) + pos] = pack_edge(vals[e], c);
    }
}

// ---------------- 3. gather SpMM: out[b, r] = sum_e v_e * xt[col_e][b] ----------------
// Proven-best structure: warp = 1 row; 4 lane-groups = 4 edge subsets;
// lane-in-group oct covers batch halves oct*8..oct*8+7 (fp16 row = 128 B =
// 8 uint4 lanes). 16 edges/iteration: 4 uniform LDG.32 packed-edge loads + 4
// independent LDG.128 gathers in flight. Groups combined with shfl_xor(8,16).
// Boustrophedon block remap keeps heavy corner-row blocks in wave 1.
// Packed entry 0 = (col 0, val 0) -> harmless padding gather.
__global__ void __launch_bounds__(512, 2) spmm_kernel(float* __restrict__ out) {
    __shared__ float tile[16 * 65];   // [row_local][b]
    const int t = threadIdx.x;
    const int warp = t >> 5;
    const int lane = t & 31;
    const int grp = lane >> 3;        // 0..3: edge subset within iteration
    const int oct = lane & 7;         // batch halves oct*8 .. oct*8+7
    // boustrophedon remap: even bids walk up from 0, odd bids walk down from nb-1
    const int nb = gridDim.x;
    const int bid = blockIdx.x;
    const int mapped = (bid & 1) ? (nb - 1 - (bid >> 1)) : (bid >> 1);
    const int r0 = mapped * 16;
    const int r = r0 + warp;

    int cnt = g_counts[r];
    if (cnt > CAP) cnt = CAP;
    const uint32_t* __restrict__ ell = &g_ell[(size_t)r << 10];
    const uint4* __restrict__ xt8 = (const uint4*)g_xt;   // [N][8] uint4

    float acc[8] = {0.f, 0.f, 0.f, 0.f, 0.f, 0.f, 0.f, 0.f};

    for (int j = 0; j < cnt; j += 16) {      // 16 edges per iteration
        float v[4];
        int   c[4];
        uint4 xv[4];
#pragma unroll
        for (int u = 0; u < 4; u++) {        // 4 packed loads, uniform per 8-lane group
            int idx = j + (u << 2) + grp;
            uint32_t e = (idx < cnt) ? __ldg(&ell[idx]) : 0u;
            c[u] = (int)(e >> 16);
            v[u] = __half2float(__ushort_as_half((unsigned short)(e & 0xFFFFu)));
        }
#pragma unroll
        for (int u = 0; u < 4; u++)          // 4 LDG.128 = 16 edges in flight
            xv[u] = __ldg(&xt8[(c[u] << 3) + oct]);
#pragma unroll
        for (int u = 0; u < 4; u++) {
            const __half2* h = (const __half2*)&xv[u];
#pragma unroll
            for (int k = 0; k < 4; k++) {
                float2 f = __half22float2(h[k]);
                acc[2 * k]     = fmaf(v[u], f.x, acc[2 * k]);
                acc[2 * k + 1] = fmaf(v[u], f.y, acc[2 * k + 1]);
            }
        }
    }

    // combine the 4 edge-subset groups (lanes l, l+8, l+16, l+24 share oct)
#pragma unroll
    for (int k = 0; k < 8; k++) {
        acc[k] += __shfl_xor_sync(0xffffffffu, acc[k], 8);
        acc[k] += __shfl_xor_sync(0xffffffffu, acc[k], 16);
    }

    if (grp == 0) {
        int base = warp * 65 + oct * 8;
#pragma unroll
        for (int k = 0; k < 8; k++) tile[base + k] = acc[k];
    }
    __syncthreads();
#pragma unroll
    for (int k = 0; k < 2; k++) {
        int idx = k * 512 + t;
        int b = idx >> 4;        // 0..63
        int c = idx & 15;        // 0..15
        out[b * NROWS + r0 + c] = tile[c * 65 + b];
    }
}

// ---------------- launch ----------------
extern "C" void kernel_launch(void* const* d_in, const int* in_sizes, int n_in,
                              void* d_out, int out_size) {
    const float* x    = (const float*)d_in[0];   // [64, 65536]
    const float* vals = (const float*)d_in[1];   // [NNZ]
    const int*   rows = (const int*)d_in[2];     // [NNZ] int32
    float* out = (float*)d_out;                  // [64, 65536]
    int nnz = in_sizes[1];

    // transpose x -> xt [N, 64] fp16  (also zeroes g_counts)
    {
        dim3 blk(32, 8);
        dim3 grd(NROWS / 32, 1);
        transpose_kernel<<<grd, blk>>>(x);
    }
    // ELL build: scatter with fused histogram (4 edges/thread; cols computed)
    int nq = nnz >> 2;
    if (nq > 0)
        scatter_kernel<<<(nq + 255) / 256, 256>>>(
            (const int4*)rows, (const float4*)vals, nq);
    int done = nq << 2;
    if (done < nnz) {
        int rem = nnz - done;
        scatter_tail_kernel<<<(rem + 255) / 256, 256>>>(rows, vals, done, nnz);
    }
    // gather SpMM
    spmm_kernel<<<NROWS / 16, 512>>>(out);
}

// round 17
// speedup vs baseline: 2.2321x; 1.0015x over previous
#include <cuda_runtime.h>
#include <cuda_fp16.h>
#include <stdint.h>

// Problem constants (fixed-shape problem)
#define NROWS 65536              // 256*256 neurons
#define BATCH 64
#define SYN   33                 // 32 random + 1 self synapse per source neuron
#define CAP   1024               // ELL row capacity (corner rows reach ~700 due to clamping)

#define NNZ_FIX   (NROWS * SYN)                 // 2,162,688
#define NQ_FIX    (NNZ_FIX / 4)                 // 540,672 quads
#define SCATTER_BLOCKS ((NQ_FIX + 255) / 256)   // 2112
#define TRANSPOSE_BLOCKS (NROWS / 32)           // 2048

// ---------------- device scratch (static; no runtime allocation) ----------------
__device__ __half   g_xt[NROWS * BATCH];         // x transposed, fp16: [N, 64] (128 B/row)
__device__ int      g_counts[NROWS];             // per-destination-row edge count
__device__ uint32_t g_ell[(size_t)NROWS * CAP];  // packed edge: (col << 16) | half(value)

__device__ __forceinline__ uint32_t pack_edge(float v, int c) {
    return ((uint32_t)c << 16) | (uint32_t)__half_as_ushort(__float2half(v));
}

// ---------------- 1. fused build: scatter (blocks 0..2111) + transpose (rest) ----------------
// Scatter (atomic/L2-sector bound) and transpose (DRAM-stream bound) use
// complementary resources; fusing overlaps the ~8us transpose under the
// ~16us scatter. g_counts is zeroed by a preceding cudaMemsetAsync node.
__global__ void build_kernel(const float* __restrict__ x,
                             const int4* __restrict__ rows4,
                             const float4* __restrict__ vals4, int nq) {
    int t = threadIdx.x;     // 0..255

    if (blockIdx.x < SCATTER_BLOCKS) {
        // ---- scatter edges into packed ELL (hist fused; 4 edges/thread) ----
        // cols structurally determined: col[e] = e / 33 (source-major repeat).
        int q = blockIdx.x * 256 + t;
        if (q < nq) {
            int4   r = rows4[q];
            float4 v = vals4[q];
            int e0 = q << 2;
            int c0 = (int)((unsigned)e0 / SYN);
            int c1 = (int)((unsigned)(e0 + 1) / SYN);
            int c2 = (int)((unsigned)(e0 + 2) / SYN);
            int c3 = (int)((unsigned)(e0 + 3) / SYN);
            // 4 independent atomic->store chains
            int p0 = atomicAdd(&g_counts[r.x], 1);
            int p1 = atomicAdd(&g_counts[r.y], 1);
            int p2 = atomicAdd(&g_counts[r.z], 1);
            int p3 = atomicAdd(&g_counts[r.w], 1);
            if (p0 < CAP) g_ell[((size_t)r.x << 10) + p0] = pack_edge(v.x, c0);
            if (p1 < CAP) g_ell[((size_t)r.y << 10) + p1] = pack_edge(v.y, c1);
            if (p2 < CAP) g_ell[((size_t)r.z << 10) + p2] = pack_edge(v.z, c2);
            if (p3 < CAP) g_ell[((size_t)r.w << 10) + p3] = pack_edge(v.w, c3);
        }
    } else {
        // ---- transpose x [64, N] -> xt [N, 64] fp16 (full 128B line writes) ----
        __shared__ float s[64][33];
        int n0 = (blockIdx.x - SCATTER_BLOCKS) * 32;
        int tx = t & 31;     // 0..31
        int ty = t >> 5;     // 0..7
#pragma unroll
        for (int k = 0; k < 8; k++) {
            int b = ty + k * 8;
            s[b][tx] = x[(size_t)b * NROWS + n0 + tx];
        }
        __syncthreads();
        unsigned int* dst = (unsigned int*)g_xt;     // [N][32] half2-as-uint
#pragma unroll
        for (int k = 0; k < 4; k++) {
            int n = ty + k * 8;                      // local neuron 0..31
            __half2 h = __floats2half2_rn(s[2 * tx][n], s[2 * tx + 1][n]);
            dst[(size_t)(n0 + n) * 32 + tx] = *(unsigned int*)&h;   // one 128B line/row
        }
    }
}

// tail (nnz not divisible by 4) — never launched for this shape, kept for safety
__global__ void scatter_tail_kernel(const int* __restrict__ rows,
                                    const float* __restrict__ vals,
                                    int start, int nnz) {
    int e = start + blockIdx.x * blockDim.x + threadIdx.x;
    if (e < nnz) {
        int r = rows[e];
        int c = (int)((unsigned)e / SYN);
        int pos = atomicAdd(&g_counts[r], 1);
        if (pos < CAP)
            g_ell[((size_t)r << 10) + pos] = pack_edge(vals[e], c);
    }
}

// ---------------- 2. gather SpMM: out[b, r] = sum_e v_e * xt[col_e][b] ----------------
// BYTE-IDENTICAL to the measured 86.1us kernel (R16): warp = 1 row; 4 lane-
// groups = 4 edge subsets; lane-in-group oct covers batch halves oct*8..
// oct*8+7 (fp16 row = 128 B = 8 uint4 lanes). 16 edges/iteration: 4 uniform
// LDG.32 packed-edge loads + 4 independent LDG.128 gathers in flight. Groups
// combined with shfl_xor(8,16). Boustrophedon block remap keeps heavy
// corner-row blocks in wave 1. Packed entry 0 -> harmless padding gather.
__global__ void __launch_bounds__(512, 2) spmm_kernel(float* __restrict__ out) {
    __shared__ float tile[16 * 65];   // [row_local][b]
    const int t = threadIdx.x;
    const int warp = t >> 5;
    const int lane = t & 31;
    const int grp = lane >> 3;        // 0..3: edge subset within iteration
    const int oct = lane & 7;         // batch halves oct*8 .. oct*8+7
    // boustrophedon remap: even bids walk up from 0, odd bids walk down from nb-1
    const int nb = gridDim.x;
    const int bid = blockIdx.x;
    const int mapped = (bid & 1) ? (nb - 1 - (bid >> 1)) : (bid >> 1);
    const int r0 = mapped * 16;
    const int r = r0 + warp;

    int cnt = g_counts[r];
    if (cnt > CAP) cnt = CAP;
    const uint32_t* __restrict__ ell = &g_ell[(size_t)r << 10];
    const uint4* __restrict__ xt8 = (const uint4*)g_xt;   // [N][8] uint4

    float acc[8] = {0.f, 0.f, 0.f, 0.f, 0.f, 0.f, 0.f, 0.f};

    for (int j = 0; j < cnt; j += 16) {      // 16 edges per iteration
        float v[4];
        int   c[4];
        uint4 xv[4];
#pragma unroll
        for (int u = 0; u < 4; u++) {        // 4 packed loads, uniform per 8-lane group
            int idx = j + (u << 2) + grp;
            uint32_t e = (idx < cnt) ? __ldg(&ell[idx]) : 0u;
            c[u] = (int)(e >> 16);
            v[u] = __half2float(__ushort_as_half((unsigned short)(e & 0xFFFFu)));
        }
#pragma unroll
        for (int u = 0; u < 4; u++)          // 4 LDG.128 = 16 edges in flight
            xv[u] = __ldg(&xt8[(c[u] << 3) + oct]);
#pragma unroll
        for (int u = 0; u < 4; u++) {
            const __half2* h = (const __half2*)&xv[u];
#pragma unroll
            for (int k = 0; k < 4; k++) {
                float2 f = __half22float2(h[k]);
                acc[2 * k]     = fmaf(v[u], f.x, acc[2 * k]);
                acc[2 * k + 1] = fmaf(v[u], f.y, acc[2 * k + 1]);
            }
        }
    }

    // combine the 4 edge-subset groups (lanes l, l+8, l+16, l+24 share oct)
#pragma unroll
    for (int k = 0; k < 8; k++) {
        acc[k] += __shfl_xor_sync(0xffffffffu, acc[k], 8);
        acc[k] += __shfl_xor_sync(0xffffffffu, acc[k], 16);
    }

    if (grp == 0) {
        int base = warp * 65 + oct * 8;
#pragma unroll
        for (int k = 0; k < 8; k++) tile[base + k] = acc[k];
    }
    __syncthreads();
#pragma unroll
    for (int k = 0; k < 2; k++) {
        int idx = k * 512 + t;
        int b = idx >> 4;        // 0..63
        int c = idx & 15;        // 0..15
        out[b * NROWS + r0 + c] = tile[c * 65 + b];
    }
}

// ---------------- launch ----------------
extern "C" void kernel_launch(void* const* d_in, const int* in_sizes, int n_in,
                              void* d_out, int out_size) {
    const float* x    = (const float*)d_in[0];   // [64, 65536]
    const float* vals = (const float*)d_in[1];   // [NNZ]
    const int*   rows = (const int*)d_in[2];     // [NNZ] int32
    float* out = (float*)d_out;                  // [64, 65536]
    int nnz = in_sizes[1];

    // zero the histogram via a memset node (graph-capturable, no allocation)
    void* cptr = nullptr;
    cudaGetSymbolAddress(&cptr, g_counts);
    cudaMemsetAsync(cptr, 0, NROWS * sizeof(int));

    // fused build: scatter (histogram fused) overlapped with fp16 transpose
    int nq = nnz >> 2;
    build_kernel<<<SCATTER_BLOCKS + TRANSPOSE_BLOCKS, 256>>>(
        x, (const int4*)rows, (const float4*)vals, nq);
    int done = nq << 2;
    if (done < nnz) {
        int rem = nnz - done;
        scatter_tail_kernel<<<(rem + 255) / 256, 256>>>(rows, vals, done, nnz);
    }
    // gather SpMM (unchanged from the 86.1us measured-best)
    spmm_kernel<<<NROWS / 16, 512>>>(out);
}